// round 14
// baseline (speedup 1.0000x reference)
#include <cuda_runtime.h>
#include <cuda_fp16.h>
#include <cstdint>

#define NN 200000
#define EE 640000
#define SB 512
#define NBLK 391   // ceil(NN / 512)
#define ZB  782    // ceil(NN / 256)
#define G128 1563  // ceil(NN / 128)
#define GG2  782   // ceil(G128 / 2): gemm blocks, 2 tiles each

// ---------------- persistent device scratch (no allocations allowed) ----------------
__device__ uint32_t g_hA[(size_t)NN * 64];
__device__ uint32_t g_hB[(size_t)NN * 64];
__device__ uint32_t g_hC[(size_t)NN * 64];    // aggregated rows, fp16 packed
__device__ uint32_t g_Wt[4][128 * 64];        // W2..W5 as fp16, transposed [n][k-pairs]
__device__ float    g_dis[NN];
__device__ int      g_cnt[NN];
__device__ int      g_row[NN + 1];
__device__ uint2    g_ce[EE];                 // packed {col, norm bits}
__device__ int      g_part[SB];
__device__ int      g_is64;

// ---------------- helpers ----------------
__device__ __forceinline__ uint32_t pack_f16(float lo, float hi) {
    __half2 h = __floats2half2_rn(lo, hi);
    return *reinterpret_cast<uint32_t*>(&h);
}

__device__ __forceinline__ float2 unpack_f16(uint32_t u) {
    __half2 h = *reinterpret_cast<__half2*>(&u);
    return __half22float2(h);
}

__device__ __forceinline__ void mma_f16(float c[4],
                                        uint32_t a0, uint32_t a1, uint32_t a2, uint32_t a3,
                                        uint32_t b0, uint32_t b1) {
    asm volatile(
        "mma.sync.aligned.m16n8k16.row.col.f32.f16.f16.f32 "
        "{%0,%1,%2,%3}, {%4,%5,%6,%7}, {%8,%9}, {%0,%1,%2,%3};\n"
        : "+f"(c[0]), "+f"(c[1]), "+f"(c[2]), "+f"(c[3])
        : "r"(a0), "r"(a1), "r"(a2), "r"(a3), "r"(b0), "r"(b1));
}

__device__ __forceinline__ int edge_at(const void* ei, int idx) {
    int v;
    if (g_is64) v = (int)((const long long*)ei)[idx];
    else        v = ((const int*)ei)[idx];
    return min(max(v, 0), NN - 1);
}

// row range under the "bumped row pointer" convention (after k_fill):
// g_row[v] holds END of node v's segment; start = v ? g_row[v-1] : 0.
__device__ __forceinline__ void row_range(int v, int& e0, int& e1) {
    e1 = g_row[v];
    e0 = (v == 0) ? 0 : g_row[v - 1];
}

// ---------------- zero + dtype probe + W conversion (merged) ----------------
__global__ void k_zero(const void* ei,
                       const float* __restrict__ W2, const float* __restrict__ W3,
                       const float* __restrict__ W4, const float* __restrict__ W5) {
    int bid = blockIdx.x;
    if (bid < ZB) {
        int i = bid * 256 + threadIdx.x;
        if (i < NN) g_cnt[i] = 0;
        if (i == 0) {
            const long long* p = (const long long*)ei;
            int ok = 1;
            #pragma unroll
            for (int j = 0; j < 4; j++) {
                long long v = p[j];
                if (v < 0 || v >= NN) ok = 0;
            }
            g_is64 = ok;
        }
    } else {
        int flat = (bid - ZB) * 256 + threadIdx.x;
        int layer, idx, KP;
        if (flat < 2048) { layer = 0; idx = flat; KP = 16; }
        else             { int f2 = flat - 2048; layer = 1 + f2 / 8192; idx = f2 % 8192; KP = 64; }
        const float* W = (layer == 0) ? W2 : (layer == 1) ? W3 : (layer == 2) ? W4 : W5;
        int n  = idx / KP;
        int kp = idx % KP;
        float lo = W[(2 * kp)     * 128 + n];
        float hi = W[(2 * kp + 1) * 128 + n];
        g_Wt[layer][n * KP + kp] = pack_f16(lo, hi);
    }
}

// ---------------- CSR build ----------------
__global__ void k_count(const void* __restrict__ ei) {
    int e = blockIdx.x * blockDim.x + threadIdx.x;
    if (e < EE) atomicAdd(&g_cnt[edge_at(ei, EE + e)], 1);
}

__global__ void k_scanA() {
    __shared__ int tmp[SB];
    int tid = threadIdx.x;
    int i = blockIdx.x * SB + tid;
    int v = (i < NN) ? g_cnt[i] : 0;
    tmp[tid] = v; __syncthreads();
    for (int off = 1; off < SB; off <<= 1) {
        int t = (tid >= off) ? tmp[tid - off] : 0;
        __syncthreads();
        if (tid >= off) tmp[tid] += t;
        __syncthreads();
    }
    if (i < NN) g_row[i + 1] = tmp[tid];
    if (tid == SB - 1) g_part[blockIdx.x] = tmp[tid];   // raw block totals
}

// scanC folds the middle scan: each block reduces g_part[0..b) itself. + g_dis.
__global__ void k_scanC() {
    __shared__ int warpsum[16];
    __shared__ int s_pre;
    int tid = threadIdx.x;
    int b = blockIdx.x;

    int part = (tid < b) ? g_part[tid] : 0;   // b <= 390 < 512
    #pragma unroll
    for (int off = 16; off; off >>= 1) part += __shfl_down_sync(0xFFFFFFFFu, part, off);
    if ((tid & 31) == 0) warpsum[tid >> 5] = part;
    __syncthreads();
    if (tid == 0) {
        int s = 0;
        #pragma unroll
        for (int w = 0; w < 16; w++) s += warpsum[w];
        s_pre = s;
    }
    __syncthreads();
    int prefix = s_pre;

    int i = b * SB + tid;
    if (i < NN) {
        g_row[i + 1] += prefix;
        if (i == 0) g_row[0] = 0;
        g_dis[i] = rsqrtf((float)g_cnt[i] + 1.0f);
    }
}

// fill bumps g_row[d] directly: afterwards g_row[d] = old start[d+1] = END of d's segment.
__global__ void k_fill(const void* __restrict__ ei) {
    int e = blockIdx.x * blockDim.x + threadIdx.x;
    if (e < EE) {
        int d = edge_at(ei, EE + e);
        int s = edge_at(ei, e);
        int p = atomicAdd(&g_row[d], 1);
        g_ce[p] = make_uint2((uint32_t)s, __float_as_uint(g_dis[s] * g_dis[d]));
    }
}

// ---------------- layer 1: aggregate x (2 feats) then [N,2]@[2,32]+b1, relu -> g_hB (fp16) ----------------
__global__ void k_layer1(const float* __restrict__ x,
                         const float* __restrict__ W1,
                         const float* __restrict__ b1) {
    __shared__ float w[64], bb[32];
    if (threadIdx.x < 64) w[threadIdx.x] = W1[threadIdx.x];
    if (threadIdx.x < 32) bb[threadIdx.x] = b1[threadIdx.x];
    __syncthreads();
    int v = blockIdx.x * blockDim.x + threadIdx.x;
    if (v >= NN) return;
    float dv = g_dis[v];
    float a0 = dv * dv * x[2 * v];
    float a1 = dv * dv * x[2 * v + 1];
    int e0, e1;
    row_range(v, e0, e1);
    for (int e = e0; e < e1; e++) {
        uint2 ce = g_ce[e];
        int s = (int)ce.x;
        float nm = __uint_as_float(ce.y);
        a0 += nm * x[2 * s];
        a1 += nm * x[2 * s + 1];
    }
    uint32_t* out = &g_hB[(size_t)v * 16];
    #pragma unroll
    for (int j = 0; j < 16; j++) {
        float r0 = fmaxf(a0 * w[2 * j]     + a1 * w[32 + 2 * j]     + bb[2 * j],     0.0f);
        float r1 = fmaxf(a0 * w[2 * j + 1] + a1 * w[32 + 2 * j + 1] + bb[2 * j + 1], 0.0f);
        out[j] = pack_f16(r0, r1);
    }
}

// ---------------- aggregation, 128 feats: 8 lanes per node (2x uint4 = 32B/lane), 4 nodes/warp ----------------
template <bool IN_A>
__global__ void __launch_bounds__(256) k_agg128() {
    const uint32_t* hin = IN_A ? g_hA : g_hB;
    int v = blockIdx.x * 32 + (threadIdx.x >> 3);   // 6250 blocks x 32 nodes = NN
    int l = threadIdx.x & 7;

    float dv = g_dis[v];
    float sn = dv * dv;
    const uint4* row = (const uint4*)(hin + (size_t)v * 64);   // 16 uint4 per row
    uint4 ua = __ldg(row + 2 * l);
    uint4 ub = __ldg(row + 2 * l + 1);
    float a[16];
    {
        float2 q;
        q = unpack_f16(ua.x); a[0]  = sn*q.x; a[1]  = sn*q.y;
        q = unpack_f16(ua.y); a[2]  = sn*q.x; a[3]  = sn*q.y;
        q = unpack_f16(ua.z); a[4]  = sn*q.x; a[5]  = sn*q.y;
        q = unpack_f16(ua.w); a[6]  = sn*q.x; a[7]  = sn*q.y;
        q = unpack_f16(ub.x); a[8]  = sn*q.x; a[9]  = sn*q.y;
        q = unpack_f16(ub.y); a[10] = sn*q.x; a[11] = sn*q.y;
        q = unpack_f16(ub.z); a[12] = sn*q.x; a[13] = sn*q.y;
        q = unpack_f16(ub.w); a[14] = sn*q.x; a[15] = sn*q.y;
    }

    int e, e1;
    row_range(v, e, e1);
    for (; e1 - e > 3; e += 2) {
        uint2 c0 = __ldg(&g_ce[e]);
        uint2 c1 = __ldg(&g_ce[e + 1]);
        float m0 = __uint_as_float(c0.y), m1 = __uint_as_float(c1.y);
        const uint4* r0 = (const uint4*)(hin + (size_t)c0.x * 64);
        const uint4* r1 = (const uint4*)(hin + (size_t)c1.x * 64);
        uint4 u0a = __ldg(r0 + 2 * l), u0b = __ldg(r0 + 2 * l + 1);
        uint4 u1a = __ldg(r1 + 2 * l), u1b = __ldg(r1 + 2 * l + 1);
        float2 q;
        q = unpack_f16(u0a.x); a[0]  += m0*q.x; a[1]  += m0*q.y;
        q = unpack_f16(u0a.y); a[2]  += m0*q.x; a[3]  += m0*q.y;
        q = unpack_f16(u0a.z); a[4]  += m0*q.x; a[5]  += m0*q.y;
        q = unpack_f16(u0a.w); a[6]  += m0*q.x; a[7]  += m0*q.y;
        q = unpack_f16(u0b.x); a[8]  += m0*q.x; a[9]  += m0*q.y;
        q = unpack_f16(u0b.y); a[10] += m0*q.x; a[11] += m0*q.y;
        q = unpack_f16(u0b.z); a[12] += m0*q.x; a[13] += m0*q.y;
        q = unpack_f16(u0b.w); a[14] += m0*q.x; a[15] += m0*q.y;
        q = unpack_f16(u1a.x); a[0]  += m1*q.x; a[1]  += m1*q.y;
        q = unpack_f16(u1a.y); a[2]  += m1*q.x; a[3]  += m1*q.y;
        q = unpack_f16(u1a.z); a[4]  += m1*q.x; a[5]  += m1*q.y;
        q = unpack_f16(u1a.w); a[6]  += m1*q.x; a[7]  += m1*q.y;
        q = unpack_f16(u1b.x); a[8]  += m1*q.x; a[9]  += m1*q.y;
        q = unpack_f16(u1b.y); a[10] += m1*q.x; a[11] += m1*q.y;
        q = unpack_f16(u1b.z); a[12] += m1*q.x; a[13] += m1*q.y;
        q = unpack_f16(u1b.w); a[14] += m1*q.x; a[15] += m1*q.y;
    }
    int rem = e1 - e;
    if (rem > 0) {
        int i1 = (rem > 1) ? e + 1 : e;
        int i2 = (rem > 2) ? e + 2 : e;
        uint2 c0 = __ldg(&g_ce[e]);
        uint2 c1 = __ldg(&g_ce[i1]);
        uint2 c2 = __ldg(&g_ce[i2]);
        float m0 = __uint_as_float(c0.y);
        float m1 = (rem > 1) ? __uint_as_float(c1.y) : 0.0f;
        float m2 = (rem > 2) ? __uint_as_float(c2.y) : 0.0f;
        const uint4* r0 = (const uint4*)(hin + (size_t)c0.x * 64);
        const uint4* r1 = (const uint4*)(hin + (size_t)c1.x * 64);
        const uint4* r2 = (const uint4*)(hin + (size_t)c2.x * 64);
        uint4 u0a = __ldg(r0 + 2 * l), u0b = __ldg(r0 + 2 * l + 1);
        uint4 u1a = __ldg(r1 + 2 * l), u1b = __ldg(r1 + 2 * l + 1);
        uint4 u2a = __ldg(r2 + 2 * l), u2b = __ldg(r2 + 2 * l + 1);
        float2 q;
        q = unpack_f16(u0a.x); a[0]  += m0*q.x; a[1]  += m0*q.y;
        q = unpack_f16(u0a.y); a[2]  += m0*q.x; a[3]  += m0*q.y;
        q = unpack_f16(u0a.z); a[4]  += m0*q.x; a[5]  += m0*q.y;
        q = unpack_f16(u0a.w); a[6]  += m0*q.x; a[7]  += m0*q.y;
        q = unpack_f16(u0b.x); a[8]  += m0*q.x; a[9]  += m0*q.y;
        q = unpack_f16(u0b.y); a[10] += m0*q.x; a[11] += m0*q.y;
        q = unpack_f16(u0b.z); a[12] += m0*q.x; a[13] += m0*q.y;
        q = unpack_f16(u0b.w); a[14] += m0*q.x; a[15] += m0*q.y;
        q = unpack_f16(u1a.x); a[0]  += m1*q.x; a[1]  += m1*q.y;
        q = unpack_f16(u1a.y); a[2]  += m1*q.x; a[3]  += m1*q.y;
        q = unpack_f16(u1a.z); a[4]  += m1*q.x; a[5]  += m1*q.y;
        q = unpack_f16(u1a.w); a[6]  += m1*q.x; a[7]  += m1*q.y;
        q = unpack_f16(u1b.x); a[8]  += m1*q.x; a[9]  += m1*q.y;
        q = unpack_f16(u1b.y); a[10] += m1*q.x; a[11] += m1*q.y;
        q = unpack_f16(u1b.z); a[12] += m1*q.x; a[13] += m1*q.y;
        q = unpack_f16(u1b.w); a[14] += m1*q.x; a[15] += m1*q.y;
        q = unpack_f16(u2a.x); a[0]  += m2*q.x; a[1]  += m2*q.y;
        q = unpack_f16(u2a.y); a[2]  += m2*q.x; a[3]  += m2*q.y;
        q = unpack_f16(u2a.z); a[4]  += m2*q.x; a[5]  += m2*q.y;
        q = unpack_f16(u2a.w); a[6]  += m2*q.x; a[7]  += m2*q.y;
        q = unpack_f16(u2b.x); a[8]  += m2*q.x; a[9]  += m2*q.y;
        q = unpack_f16(u2b.y); a[10] += m2*q.x; a[11] += m2*q.y;
        q = unpack_f16(u2b.z); a[12] += m2*q.x; a[13] += m2*q.y;
        q = unpack_f16(u2b.w); a[14] += m2*q.x; a[15] += m2*q.y;
    }

    uint4 ta, tb;
    ta.x = pack_f16(a[0],  a[1]);  ta.y = pack_f16(a[2],  a[3]);
    ta.z = pack_f16(a[4],  a[5]);  ta.w = pack_f16(a[6],  a[7]);
    tb.x = pack_f16(a[8],  a[9]);  tb.y = pack_f16(a[10], a[11]);
    tb.z = pack_f16(a[12], a[13]); tb.w = pack_f16(a[14], a[15]);
    uint4* orow = (uint4*)(g_hC + (size_t)v * 64);
    orow[2 * l]     = ta;
    orow[2 * l + 1] = tb;
}

// ---------------- aggregation, 32 feats: 8 lanes per node (uint2 = 8B/lane), 4 nodes/warp ----------------
__global__ void __launch_bounds__(256) k_agg32() {
    const uint32_t* hin = g_hB;
    int v = blockIdx.x * 32 + (threadIdx.x >> 3);   // 6250 blocks
    int l = threadIdx.x & 7;

    float dv = g_dis[v];
    float sn = dv * dv;
    uint2 u = __ldg((const uint2*)(hin + (size_t)v * 16) + l);
    float2 p0 = unpack_f16(u.x), p1 = unpack_f16(u.y);
    float a0 = sn*p0.x, a1 = sn*p0.y, a2 = sn*p1.x, a3 = sn*p1.y;

    int e, e1;
    row_range(v, e, e1);
    for (; e1 - e > 3; e += 2) {
        uint2 c0 = __ldg(&g_ce[e]);
        uint2 c1 = __ldg(&g_ce[e + 1]);
        float m0 = __uint_as_float(c0.y), m1 = __uint_as_float(c1.y);
        uint2 u0 = __ldg((const uint2*)(hin + (size_t)c0.x * 16) + l);
        uint2 u1 = __ldg((const uint2*)(hin + (size_t)c1.x * 16) + l);
        float2 q;
        q = unpack_f16(u0.x); a0 += m0*q.x; a1 += m0*q.y;
        q = unpack_f16(u0.y); a2 += m0*q.x; a3 += m0*q.y;
        q = unpack_f16(u1.x); a0 += m1*q.x; a1 += m1*q.y;
        q = unpack_f16(u1.y); a2 += m1*q.x; a3 += m1*q.y;
    }
    int rem = e1 - e;
    if (rem > 0) {
        int i1 = (rem > 1) ? e + 1 : e;
        int i2 = (rem > 2) ? e + 2 : e;
        uint2 c0 = __ldg(&g_ce[e]);
        uint2 c1 = __ldg(&g_ce[i1]);
        uint2 c2 = __ldg(&g_ce[i2]);
        float m0 = __uint_as_float(c0.y);
        float m1 = (rem > 1) ? __uint_as_float(c1.y) : 0.0f;
        float m2 = (rem > 2) ? __uint_as_float(c2.y) : 0.0f;
        uint2 u0 = __ldg((const uint2*)(hin + (size_t)c0.x * 16) + l);
        uint2 u1 = __ldg((const uint2*)(hin + (size_t)c1.x * 16) + l);
        uint2 u2 = __ldg((const uint2*)(hin + (size_t)c2.x * 16) + l);
        float2 q;
        q = unpack_f16(u0.x); a0 += m0*q.x; a1 += m0*q.y;
        q = unpack_f16(u0.y); a2 += m0*q.x; a3 += m0*q.y;
        q = unpack_f16(u1.x); a0 += m1*q.x; a1 += m1*q.y;
        q = unpack_f16(u1.y); a2 += m1*q.x; a3 += m1*q.y;
        q = unpack_f16(u2.x); a0 += m2*q.x; a1 += m2*q.y;
        q = unpack_f16(u2.y); a2 += m2*q.x; a3 += m2*q.y;
    }

    uint2 t;
    t.x = pack_f16(a0, a1);
    t.y = pack_f16(a2, a3);
    ((uint2*)(g_hC + (size_t)v * 16))[l] = t;
}

// ---------------- GEMM: [128,FIN] fp16 @ [FIN,128] fp16 + b; 2 tiles per block, W staged once ----------------
// 512 threads, GG2 blocks. OUTSEL: 0 -> hA, 1 -> hB, 2 -> fused final.
template <int FIN, int LAYER, int OUTSEL>
__global__ void __launch_bounds__(512) k_gemm(const float* __restrict__ b,
                                              const float* __restrict__ Wl,
                                              const float* __restrict__ bl,
                                              float* __restrict__ out) {
    constexpr int KP  = FIN / 2;
    constexpr int WSW = KP + 4;
    constexpr int ASW = KP + 4;
    extern __shared__ uint32_t smU[];
    uint32_t* Ws = smU;                 // [128][WSW]
    uint32_t* As = smU + 128 * WSW;     // [128][ASW]
    uint32_t* hout = (OUTSEL == 0) ? g_hA : g_hB;

    const int tid  = threadIdx.x;
    const int wid  = tid >> 5;
    const int lane = tid & 31;

    // ---- stage W once per block ----
    {
        const uint4* Wg = (const uint4*)g_Wt[LAYER];
        constexpr int C4 = KP / 4;
        for (int idx4 = tid; idx4 < 128 * C4; idx4 += 512) {
            int n  = idx4 / C4;
            int c4 = idx4 % C4;
            *(uint4*)&Ws[n * WSW + 4 * c4] = __ldg(&Wg[idx4]);
        }
    }

    const int rowt = wid & 3;
    const int colt = wid >> 2;
    const int r_base = rowt * 32;
    const int n_base = colt * 32;
    const int group = lane >> 2;
    const int tig   = lane & 3;

    #pragma unroll
    for (int t = 0; t < 2; t++) {
        const int tile = blockIdx.x * 2 + t;
        if (tile >= G128) break;
        const int base_row = tile * 128;

        // ---- stage A tile (128 rows, fp16) with row clamp ----
        {
            constexpr int C4 = KP / 4;
            for (int idx4 = tid; idx4 < 128 * C4; idx4 += 512) {
                int r  = idx4 / C4;
                int c4 = idx4 % C4;
                int rg = min(base_row + r, NN - 1);
                uint4 val = __ldg((const uint4*)(g_hC + (size_t)rg * KP) + c4);
                *(uint4*)&As[r * ASW + 4 * c4] = val;
            }
        }
        __syncthreads();

        float C[2][4][4];
        #pragma unroll
        for (int mi = 0; mi < 2; mi++)
            #pragma unroll
            for (int ni = 0; ni < 4; ni++)
                #pragma unroll
                for (int j = 0; j < 4; j++) C[mi][ni][j] = 0.0f;

        #pragma unroll
        for (int kk = 0; kk < FIN; kk += 16) {
            int kbase = kk >> 1;
            uint32_t a[2][4];
            #pragma unroll
            for (int mi = 0; mi < 2; mi++) {
                int r0 = r_base + mi * 16 + group;
                a[mi][0] = As[r0 * ASW + kbase + tig];
                a[mi][1] = As[(r0 + 8) * ASW + kbase + tig];
                a[mi][2] = As[r0 * ASW + kbase + tig + 4];
                a[mi][3] = As[(r0 + 8) * ASW + kbase + tig + 4];
            }
            #pragma unroll
            for (int ni = 0; ni < 4; ni++) {
                int nc = n_base + ni * 8 + group;
                uint32_t b0 = Ws[nc * WSW + kbase + tig];
                uint32_t b1 = Ws[nc * WSW + kbase + tig + 4];
                mma_f16(C[0][ni], a[0][0], a[0][1], a[0][2], a[0][3], b0, b1);
                mma_f16(C[1][ni], a[1][0], a[1][1], a[1][2], a[1][3], b0, b1);
            }
        }

        if (OUTSEL != 2) {
            #pragma unroll
            for (int ni = 0; ni < 4; ni++) {
                int col = n_base + ni * 8 + 2 * tig;
                float2 bb = __ldg((const float2*)&b[col]);
                #pragma unroll
                for (int mi = 0; mi < 2; mi++) {
                    int row0 = base_row + r_base + mi * 16 + group;
                    float o00 = fmaxf(C[mi][ni][0] + bb.x, 0.0f);
                    float o01 = fmaxf(C[mi][ni][1] + bb.y, 0.0f);
                    float o10 = fmaxf(C[mi][ni][2] + bb.x, 0.0f);
                    float o11 = fmaxf(C[mi][ni][3] + bb.y, 0.0f);
                    if (row0 < NN)     hout[(size_t)row0 * 64 + (col >> 1)]       = pack_f16(o00, o01);
                    if (row0 + 8 < NN) hout[(size_t)(row0 + 8) * 64 + (col >> 1)] = pack_f16(o10, o11);
                }
            }
        } else {
            float* rowsum = (float*)As;
            __syncthreads();
            if (tid < 128) rowsum[tid] = 0.0f;
            __syncthreads();
            #pragma unroll
            for (int mi = 0; mi < 2; mi++) {
                #pragma unroll
                for (int half = 0; half < 2; half++) {
                    float partial = 0.0f;
                    #pragma unroll
                    for (int ni = 0; ni < 4; ni++) {
                        int col = n_base + ni * 8 + 2 * tig;
                        float2 bb = __ldg((const float2*)&b[col]);
                        float v0 = fmaxf(C[mi][ni][2 * half]     + bb.x, 0.0f);
                        float v1 = fmaxf(C[mi][ni][2 * half + 1] + bb.y, 0.0f);
                        float2 wl = __ldg((const float2*)&Wl[col]);
                        partial += v0 * wl.x + v1 * wl.y;
                    }
                    partial += __shfl_xor_sync(0xFFFFFFFFu, partial, 1);
                    partial += __shfl_xor_sync(0xFFFFFFFFu, partial, 2);
                    if (tig == 0) {
                        int rloc = r_base + mi * 16 + group + 8 * half;
                        atomicAdd(&rowsum[rloc], partial);
                    }
                }
            }
            __syncthreads();
            if (tid < 128) {
                int row = base_row + tid;
                if (row < NN) {
                    float s = rowsum[tid] + __ldg(bl);
                    out[row] = (s > 0.0f) ? s : 0.01f * s;
                }
            }
        }
        __syncthreads();   // protect As before next tile's staging
    }
}

// ---------------- launch ----------------
extern "C" void kernel_launch(void* const* d_in, const int* in_sizes, int n_in,
                              void* d_out, int out_size) {
    int ix = 0, ie = 1, iW1 = 2, ib1 = 3, iW2 = 4, ib2 = 5, iW3 = 6, ib3 = 7,
        iW4 = 8, ib4 = 9, iW5 = 10, ib5 = 11, iWl = 12, ibl = 13;
    if (n_in >= 14 && in_sizes[0] != 2 * NN) {
        if (in_sizes[0] == 64 && in_sizes[1] == 4096) {
            iW1 = 0; iW2 = 1; iW3 = 2; iW4 = 3; iW5 = 4; iWl = 5;
            ib1 = 6; ib2 = 7; ib3 = 8; ib4 = 9; ib5 = 10; ibl = 11;
            ie = 12; ix = 13;
        }
    }

    const float* x  = (const float*)d_in[ix];
    const void*  ei = d_in[ie];
    const float* W1 = (const float*)d_in[iW1];
    const float* b1 = (const float*)d_in[ib1];
    const float* W2 = (const float*)d_in[iW2];
    const float* b2 = (const float*)d_in[ib2];
    const float* W3 = (const float*)d_in[iW3];
    const float* b3 = (const float*)d_in[ib3];
    const float* W4 = (const float*)d_in[iW4];
    const float* b4 = (const float*)d_in[ib4];
    const float* W5 = (const float*)d_in[iW5];
    const float* b5 = (const float*)d_in[ib5];
    const float* Wl = (const float*)d_in[iWl];
    const float* bl = (const float*)d_in[ibl];
    float* out = (float*)d_out;

    const int sh32  = (128 * 20 + 128 * 20) * 4;   // 20,480 B
    const int sh128 = (128 * 68 + 128 * 68) * 4;   // 69,632 B
    cudaFuncSetAttribute(k_gemm<32,  0, 0>, cudaFuncAttributeMaxDynamicSharedMemorySize, sh32);
    cudaFuncSetAttribute(k_gemm<128, 1, 1>, cudaFuncAttributeMaxDynamicSharedMemorySize, sh128);
    cudaFuncSetAttribute(k_gemm<128, 2, 0>, cudaFuncAttributeMaxDynamicSharedMemorySize, sh128);
    cudaFuncSetAttribute(k_gemm<128, 3, 2>, cudaFuncAttributeMaxDynamicSharedMemorySize, sh128);

    // CSR + norms + W conversion
    k_zero <<<ZB + 104, 256>>>(ei, W2, W3, W4, W5);
    k_count<<<(EE + 255) / 256, 256>>>(ei);
    k_scanA<<<NBLK, SB>>>();
    k_scanC<<<NBLK, SB>>>();                 // folded middle scan + g_dis
    k_fill <<<(EE + 255) / 256, 256>>>(ei); // bumps g_row -> END-pointer convention

    // layers
    k_layer1<<<(NN + 255) / 256, 256>>>(x, W1, b1);             // x  -> hB [N,32] fp16
    k_agg32 <<<NN / 32, 256>>>();                               // hB -> C
    k_gemm<32,  0, 0><<<GG2, 512, sh32 >>>(b2, Wl, bl, out);    // C  -> hA
    k_agg128<true ><<<NN / 32, 256>>>();                        // hA -> C
    k_gemm<128, 1, 1><<<GG2, 512, sh128>>>(b3, Wl, bl, out);    // C  -> hB
    k_agg128<false><<<NN / 32, 256>>>();                        // hB -> C
    k_gemm<128, 2, 0><<<GG2, 512, sh128>>>(b4, Wl, bl, out);    // C  -> hA
    k_agg128<true ><<<NN / 32, 256>>>();                        // hA -> C
    k_gemm<128, 3, 2><<<GG2, 512, sh128>>>(b5, Wl, bl, out);    // C  -> out (fused final)
}

// round 15
// speedup vs baseline: 1.0642x; 1.0642x over previous
#include <cuda_runtime.h>
#include <cuda_fp16.h>
#include <cstdint>

#define NN 200000
#define EE 640000
#define SB 512
#define NBLK 391   // ceil(NN / 512)
#define ZB  782    // ceil(NN / 256)
#define G128 1563  // ceil(NN / 128)

// ---------------- persistent device scratch (no allocations allowed) ----------------
__device__ uint32_t g_hA[(size_t)NN * 64];
__device__ uint32_t g_hB[(size_t)NN * 64];
__device__ uint32_t g_hC[(size_t)NN * 64];    // aggregated rows, fp16 packed
__device__ uint32_t g_Wt[4][128 * 64];        // W2..W5 as fp16, transposed [n][k-pairs]
__device__ float    g_dis[NN];
__device__ int      g_cnt[NN];
__device__ int      g_row[NN + 1];
__device__ uint2    g_ce[EE];                 // packed {col, norm bits}
__device__ int      g_part[SB];
__device__ int      g_is64;

// ---------------- helpers ----------------
__device__ __forceinline__ uint32_t pack_f16(float lo, float hi) {
    __half2 h = __floats2half2_rn(lo, hi);
    return *reinterpret_cast<uint32_t*>(&h);
}

__device__ __forceinline__ float2 unpack_f16(uint32_t u) {
    __half2 h = *reinterpret_cast<__half2*>(&u);
    return __half22float2(h);
}

__device__ __forceinline__ void mma_f16(float c[4],
                                        uint32_t a0, uint32_t a1, uint32_t a2, uint32_t a3,
                                        uint32_t b0, uint32_t b1) {
    asm volatile(
        "mma.sync.aligned.m16n8k16.row.col.f32.f16.f16.f32 "
        "{%0,%1,%2,%3}, {%4,%5,%6,%7}, {%8,%9}, {%0,%1,%2,%3};\n"
        : "+f"(c[0]), "+f"(c[1]), "+f"(c[2]), "+f"(c[3])
        : "r"(a0), "r"(a1), "r"(a2), "r"(a3), "r"(b0), "r"(b1));
}

__device__ __forceinline__ int edge_at(const void* ei, int idx) {
    int v;
    if (g_is64) v = (int)((const long long*)ei)[idx];
    else        v = ((const int*)ei)[idx];
    return min(max(v, 0), NN - 1);
}

// row range under the "bumped row pointer" convention (after k_fill):
// g_row[v] holds END of node v's segment; start = v ? g_row[v-1] : 0.
__device__ __forceinline__ void row_range(int v, int& e0, int& e1) {
    e1 = g_row[v];
    e0 = (v == 0) ? 0 : g_row[v - 1];
}

// ---------------- zero + dtype probe + W conversion (merged) ----------------
__global__ void k_zero(const void* ei,
                       const float* __restrict__ W2, const float* __restrict__ W3,
                       const float* __restrict__ W4, const float* __restrict__ W5) {
    int bid = blockIdx.x;
    if (bid < ZB) {
        int i = bid * 256 + threadIdx.x;
        if (i < NN) g_cnt[i] = 0;
        if (i == 0) {
            const long long* p = (const long long*)ei;
            int ok = 1;
            #pragma unroll
            for (int j = 0; j < 4; j++) {
                long long v = p[j];
                if (v < 0 || v >= NN) ok = 0;
            }
            g_is64 = ok;
        }
    } else {
        int flat = (bid - ZB) * 256 + threadIdx.x;
        int layer, idx, KP;
        if (flat < 2048) { layer = 0; idx = flat; KP = 16; }
        else             { int f2 = flat - 2048; layer = 1 + f2 / 8192; idx = f2 % 8192; KP = 64; }
        const float* W = (layer == 0) ? W2 : (layer == 1) ? W3 : (layer == 2) ? W4 : W5;
        int n  = idx / KP;
        int kp = idx % KP;
        float lo = W[(2 * kp)     * 128 + n];
        float hi = W[(2 * kp + 1) * 128 + n];
        g_Wt[layer][n * KP + kp] = pack_f16(lo, hi);
    }
}

// ---------------- CSR build ----------------
__global__ void k_count(const void* __restrict__ ei) {
    int e = blockIdx.x * blockDim.x + threadIdx.x;
    if (e < EE) atomicAdd(&g_cnt[edge_at(ei, EE + e)], 1);
}

__global__ void k_scanA() {
    __shared__ int tmp[SB];
    int tid = threadIdx.x;
    int i = blockIdx.x * SB + tid;
    int v = (i < NN) ? g_cnt[i] : 0;
    tmp[tid] = v; __syncthreads();
    for (int off = 1; off < SB; off <<= 1) {
        int t = (tid >= off) ? tmp[tid - off] : 0;
        __syncthreads();
        if (tid >= off) tmp[tid] += t;
        __syncthreads();
    }
    if (i < NN) g_row[i + 1] = tmp[tid];
    if (tid == SB - 1) g_part[blockIdx.x] = tmp[tid];   // raw block totals
}

// scanC folds the middle scan: each block reduces g_part[0..b) itself. + g_dis.
__global__ void k_scanC() {
    __shared__ int warpsum[16];
    __shared__ int s_pre;
    int tid = threadIdx.x;
    int b = blockIdx.x;

    int part = (tid < b) ? g_part[tid] : 0;   // b <= 390 < 512
    #pragma unroll
    for (int off = 16; off; off >>= 1) part += __shfl_down_sync(0xFFFFFFFFu, part, off);
    if ((tid & 31) == 0) warpsum[tid >> 5] = part;
    __syncthreads();
    if (tid == 0) {
        int s = 0;
        #pragma unroll
        for (int w = 0; w < 16; w++) s += warpsum[w];
        s_pre = s;
    }
    __syncthreads();
    int prefix = s_pre;

    int i = b * SB + tid;
    if (i < NN) {
        g_row[i + 1] += prefix;
        if (i == 0) g_row[0] = 0;
        g_dis[i] = rsqrtf((float)g_cnt[i] + 1.0f);
    }
}

// fill bumps g_row[d] directly: afterwards g_row[d] = old start[d+1] = END of d's segment.
__global__ void k_fill(const void* __restrict__ ei) {
    int e = blockIdx.x * blockDim.x + threadIdx.x;
    if (e < EE) {
        int d = edge_at(ei, EE + e);
        int s = edge_at(ei, e);
        int p = atomicAdd(&g_row[d], 1);
        g_ce[p] = make_uint2((uint32_t)s, __float_as_uint(g_dis[s] * g_dis[d]));
    }
}

// ---------------- layer 1: aggregate x (2 feats) then [N,2]@[2,32]+b1, relu -> g_hB (fp16) ----------------
__global__ void k_layer1(const float* __restrict__ x,
                         const float* __restrict__ W1,
                         const float* __restrict__ b1) {
    __shared__ float w[64], bb[32];
    if (threadIdx.x < 64) w[threadIdx.x] = W1[threadIdx.x];
    if (threadIdx.x < 32) bb[threadIdx.x] = b1[threadIdx.x];
    __syncthreads();
    int v = blockIdx.x * blockDim.x + threadIdx.x;
    if (v >= NN) return;
    float dv = g_dis[v];
    float a0 = dv * dv * x[2 * v];
    float a1 = dv * dv * x[2 * v + 1];
    int e0, e1;
    row_range(v, e0, e1);
    for (int e = e0; e < e1; e++) {
        uint2 ce = g_ce[e];
        int s = (int)ce.x;
        float nm = __uint_as_float(ce.y);
        a0 += nm * x[2 * s];
        a1 += nm * x[2 * s + 1];
    }
    uint32_t* out = &g_hB[(size_t)v * 16];
    #pragma unroll
    for (int j = 0; j < 16; j++) {
        float r0 = fmaxf(a0 * w[2 * j]     + a1 * w[32 + 2 * j]     + bb[2 * j],     0.0f);
        float r1 = fmaxf(a0 * w[2 * j + 1] + a1 * w[32 + 2 * j + 1] + bb[2 * j + 1], 0.0f);
        out[j] = pack_f16(r0, r1);
    }
}

// ---------------- aggregation, 128 feats: 8 lanes per node (2x uint4 = 32B/lane), 4 nodes/warp ----------------
template <bool IN_A>
__global__ void __launch_bounds__(256) k_agg128() {
    const uint32_t* hin = IN_A ? g_hA : g_hB;
    int v = blockIdx.x * 32 + (threadIdx.x >> 3);   // 6250 blocks x 32 nodes = NN
    int l = threadIdx.x & 7;

    float dv = g_dis[v];
    float sn = dv * dv;
    const uint4* row = (const uint4*)(hin + (size_t)v * 64);   // 16 uint4 per row
    uint4 ua = __ldg(row + 2 * l);
    uint4 ub = __ldg(row + 2 * l + 1);
    float a[16];
    {
        float2 q;
        q = unpack_f16(ua.x); a[0]  = sn*q.x; a[1]  = sn*q.y;
        q = unpack_f16(ua.y); a[2]  = sn*q.x; a[3]  = sn*q.y;
        q = unpack_f16(ua.z); a[4]  = sn*q.x; a[5]  = sn*q.y;
        q = unpack_f16(ua.w); a[6]  = sn*q.x; a[7]  = sn*q.y;
        q = unpack_f16(ub.x); a[8]  = sn*q.x; a[9]  = sn*q.y;
        q = unpack_f16(ub.y); a[10] = sn*q.x; a[11] = sn*q.y;
        q = unpack_f16(ub.z); a[12] = sn*q.x; a[13] = sn*q.y;
        q = unpack_f16(ub.w); a[14] = sn*q.x; a[15] = sn*q.y;
    }

    int e, e1;
    row_range(v, e, e1);
    for (; e1 - e > 3; e += 2) {
        uint2 c0 = __ldg(&g_ce[e]);
        uint2 c1 = __ldg(&g_ce[e + 1]);
        float m0 = __uint_as_float(c0.y), m1 = __uint_as_float(c1.y);
        const uint4* r0 = (const uint4*)(hin + (size_t)c0.x * 64);
        const uint4* r1 = (const uint4*)(hin + (size_t)c1.x * 64);
        uint4 u0a = __ldg(r0 + 2 * l), u0b = __ldg(r0 + 2 * l + 1);
        uint4 u1a = __ldg(r1 + 2 * l), u1b = __ldg(r1 + 2 * l + 1);
        float2 q;
        q = unpack_f16(u0a.x); a[0]  += m0*q.x; a[1]  += m0*q.y;
        q = unpack_f16(u0a.y); a[2]  += m0*q.x; a[3]  += m0*q.y;
        q = unpack_f16(u0a.z); a[4]  += m0*q.x; a[5]  += m0*q.y;
        q = unpack_f16(u0a.w); a[6]  += m0*q.x; a[7]  += m0*q.y;
        q = unpack_f16(u0b.x); a[8]  += m0*q.x; a[9]  += m0*q.y;
        q = unpack_f16(u0b.y); a[10] += m0*q.x; a[11] += m0*q.y;
        q = unpack_f16(u0b.z); a[12] += m0*q.x; a[13] += m0*q.y;
        q = unpack_f16(u0b.w); a[14] += m0*q.x; a[15] += m0*q.y;
        q = unpack_f16(u1a.x); a[0]  += m1*q.x; a[1]  += m1*q.y;
        q = unpack_f16(u1a.y); a[2]  += m1*q.x; a[3]  += m1*q.y;
        q = unpack_f16(u1a.z); a[4]  += m1*q.x; a[5]  += m1*q.y;
        q = unpack_f16(u1a.w); a[6]  += m1*q.x; a[7]  += m1*q.y;
        q = unpack_f16(u1b.x); a[8]  += m1*q.x; a[9]  += m1*q.y;
        q = unpack_f16(u1b.y); a[10] += m1*q.x; a[11] += m1*q.y;
        q = unpack_f16(u1b.z); a[12] += m1*q.x; a[13] += m1*q.y;
        q = unpack_f16(u1b.w); a[14] += m1*q.x; a[15] += m1*q.y;
    }
    int rem = e1 - e;
    if (rem > 0) {
        int i1 = (rem > 1) ? e + 1 : e;
        int i2 = (rem > 2) ? e + 2 : e;
        uint2 c0 = __ldg(&g_ce[e]);
        uint2 c1 = __ldg(&g_ce[i1]);
        uint2 c2 = __ldg(&g_ce[i2]);
        float m0 = __uint_as_float(c0.y);
        float m1 = (rem > 1) ? __uint_as_float(c1.y) : 0.0f;
        float m2 = (rem > 2) ? __uint_as_float(c2.y) : 0.0f;
        const uint4* r0 = (const uint4*)(hin + (size_t)c0.x * 64);
        const uint4* r1 = (const uint4*)(hin + (size_t)c1.x * 64);
        const uint4* r2 = (const uint4*)(hin + (size_t)c2.x * 64);
        uint4 u0a = __ldg(r0 + 2 * l), u0b = __ldg(r0 + 2 * l + 1);
        uint4 u1a = __ldg(r1 + 2 * l), u1b = __ldg(r1 + 2 * l + 1);
        uint4 u2a = __ldg(r2 + 2 * l), u2b = __ldg(r2 + 2 * l + 1);
        float2 q;
        q = unpack_f16(u0a.x); a[0]  += m0*q.x; a[1]  += m0*q.y;
        q = unpack_f16(u0a.y); a[2]  += m0*q.x; a[3]  += m0*q.y;
        q = unpack_f16(u0a.z); a[4]  += m0*q.x; a[5]  += m0*q.y;
        q = unpack_f16(u0a.w); a[6]  += m0*q.x; a[7]  += m0*q.y;
        q = unpack_f16(u0b.x); a[8]  += m0*q.x; a[9]  += m0*q.y;
        q = unpack_f16(u0b.y); a[10] += m0*q.x; a[11] += m0*q.y;
        q = unpack_f16(u0b.z); a[12] += m0*q.x; a[13] += m0*q.y;
        q = unpack_f16(u0b.w); a[14] += m0*q.x; a[15] += m0*q.y;
        q = unpack_f16(u1a.x); a[0]  += m1*q.x; a[1]  += m1*q.y;
        q = unpack_f16(u1a.y); a[2]  += m1*q.x; a[3]  += m1*q.y;
        q = unpack_f16(u1a.z); a[4]  += m1*q.x; a[5]  += m1*q.y;
        q = unpack_f16(u1a.w); a[6]  += m1*q.x; a[7]  += m1*q.y;
        q = unpack_f16(u1b.x); a[8]  += m1*q.x; a[9]  += m1*q.y;
        q = unpack_f16(u1b.y); a[10] += m1*q.x; a[11] += m1*q.y;
        q = unpack_f16(u1b.z); a[12] += m1*q.x; a[13] += m1*q.y;
        q = unpack_f16(u1b.w); a[14] += m1*q.x; a[15] += m1*q.y;
        q = unpack_f16(u2a.x); a[0]  += m2*q.x; a[1]  += m2*q.y;
        q = unpack_f16(u2a.y); a[2]  += m2*q.x; a[3]  += m2*q.y;
        q = unpack_f16(u2a.z); a[4]  += m2*q.x; a[5]  += m2*q.y;
        q = unpack_f16(u2a.w); a[6]  += m2*q.x; a[7]  += m2*q.y;
        q = unpack_f16(u2b.x); a[8]  += m2*q.x; a[9]  += m2*q.y;
        q = unpack_f16(u2b.y); a[10] += m2*q.x; a[11] += m2*q.y;
        q = unpack_f16(u2b.z); a[12] += m2*q.x; a[13] += m2*q.y;
        q = unpack_f16(u2b.w); a[14] += m2*q.x; a[15] += m2*q.y;
    }

    uint4 ta, tb;
    ta.x = pack_f16(a[0],  a[1]);  ta.y = pack_f16(a[2],  a[3]);
    ta.z = pack_f16(a[4],  a[5]);  ta.w = pack_f16(a[6],  a[7]);
    tb.x = pack_f16(a[8],  a[9]);  tb.y = pack_f16(a[10], a[11]);
    tb.z = pack_f16(a[12], a[13]); tb.w = pack_f16(a[14], a[15]);
    uint4* orow = (uint4*)(g_hC + (size_t)v * 64);
    orow[2 * l]     = ta;
    orow[2 * l + 1] = tb;
}

// ---------------- aggregation, 32 feats: 8 lanes per node (uint2 = 8B/lane), 4 nodes/warp ----------------
__global__ void __launch_bounds__(256) k_agg32() {
    const uint32_t* hin = g_hB;
    int v = blockIdx.x * 32 + (threadIdx.x >> 3);   // 6250 blocks
    int l = threadIdx.x & 7;

    float dv = g_dis[v];
    float sn = dv * dv;
    uint2 u = __ldg((const uint2*)(hin + (size_t)v * 16) + l);
    float2 p0 = unpack_f16(u.x), p1 = unpack_f16(u.y);
    float a0 = sn*p0.x, a1 = sn*p0.y, a2 = sn*p1.x, a3 = sn*p1.y;

    int e, e1;
    row_range(v, e, e1);
    for (; e1 - e > 3; e += 2) {
        uint2 c0 = __ldg(&g_ce[e]);
        uint2 c1 = __ldg(&g_ce[e + 1]);
        float m0 = __uint_as_float(c0.y), m1 = __uint_as_float(c1.y);
        uint2 u0 = __ldg((const uint2*)(hin + (size_t)c0.x * 16) + l);
        uint2 u1 = __ldg((const uint2*)(hin + (size_t)c1.x * 16) + l);
        float2 q;
        q = unpack_f16(u0.x); a0 += m0*q.x; a1 += m0*q.y;
        q = unpack_f16(u0.y); a2 += m0*q.x; a3 += m0*q.y;
        q = unpack_f16(u1.x); a0 += m1*q.x; a1 += m1*q.y;
        q = unpack_f16(u1.y); a2 += m1*q.x; a3 += m1*q.y;
    }
    int rem = e1 - e;
    if (rem > 0) {
        int i1 = (rem > 1) ? e + 1 : e;
        int i2 = (rem > 2) ? e + 2 : e;
        uint2 c0 = __ldg(&g_ce[e]);
        uint2 c1 = __ldg(&g_ce[i1]);
        uint2 c2 = __ldg(&g_ce[i2]);
        float m0 = __uint_as_float(c0.y);
        float m1 = (rem > 1) ? __uint_as_float(c1.y) : 0.0f;
        float m2 = (rem > 2) ? __uint_as_float(c2.y) : 0.0f;
        uint2 u0 = __ldg((const uint2*)(hin + (size_t)c0.x * 16) + l);
        uint2 u1 = __ldg((const uint2*)(hin + (size_t)c1.x * 16) + l);
        uint2 u2 = __ldg((const uint2*)(hin + (size_t)c2.x * 16) + l);
        float2 q;
        q = unpack_f16(u0.x); a0 += m0*q.x; a1 += m0*q.y;
        q = unpack_f16(u0.y); a2 += m0*q.x; a3 += m0*q.y;
        q = unpack_f16(u1.x); a0 += m1*q.x; a1 += m1*q.y;
        q = unpack_f16(u1.y); a2 += m1*q.x; a3 += m1*q.y;
        q = unpack_f16(u2.x); a0 += m2*q.x; a1 += m2*q.y;
        q = unpack_f16(u2.y); a2 += m2*q.x; a3 += m2*q.y;
    }

    uint2 t;
    t.x = pack_f16(a0, a1);
    t.y = pack_f16(a2, a3);
    ((uint2*)(g_hC + (size_t)v * 16))[l] = t;
}

// ---------------- GEMM (single tile per block, R13 form): [128,FIN] fp16 @ [FIN,128] fp16 + b ----------------
// 512 threads, G128 blocks. OUTSEL: 0 -> hA, 1 -> hB, 2 -> fused final.
template <int FIN, int LAYER, int OUTSEL>
__global__ void __launch_bounds__(512) k_gemm(const float* __restrict__ b,
                                              const float* __restrict__ Wl,
                                              const float* __restrict__ bl,
                                              float* __restrict__ out) {
    constexpr int KP  = FIN / 2;
    constexpr int WSW = KP + 4;
    constexpr int ASW = KP + 4;
    extern __shared__ uint32_t smU[];
    uint32_t* Ws = smU;                 // [128][WSW]
    uint32_t* As = smU + 128 * WSW;     // [128][ASW]
    uint32_t* hout = (OUTSEL == 0) ? g_hA : g_hB;

    const int tid  = threadIdx.x;
    const int wid  = tid >> 5;
    const int lane = tid & 31;
    const int base_row = blockIdx.x * 128;

    {
        const uint4* Wg = (const uint4*)g_Wt[LAYER];
        constexpr int C4 = KP / 4;
        for (int idx4 = tid; idx4 < 128 * C4; idx4 += 512) {
            int n  = idx4 / C4;
            int c4 = idx4 % C4;
            *(uint4*)&Ws[n * WSW + 4 * c4] = __ldg(&Wg[idx4]);
        }
    }
    {
        constexpr int C4 = KP / 4;
        for (int idx4 = tid; idx4 < 128 * C4; idx4 += 512) {
            int r  = idx4 / C4;
            int c4 = idx4 % C4;
            int rg = min(base_row + r, NN - 1);
            uint4 val = __ldg((const uint4*)(g_hC + (size_t)rg * KP) + c4);
            *(uint4*)&As[r * ASW + 4 * c4] = val;
        }
    }
    __syncthreads();

    const int rowt = wid & 3;
    const int colt = wid >> 2;
    const int r_base = rowt * 32;
    const int n_base = colt * 32;
    const int group = lane >> 2;
    const int tig   = lane & 3;

    float C[2][4][4];
    #pragma unroll
    for (int mi = 0; mi < 2; mi++)
        #pragma unroll
        for (int ni = 0; ni < 4; ni++)
            #pragma unroll
            for (int j = 0; j < 4; j++) C[mi][ni][j] = 0.0f;

    #pragma unroll
    for (int kk = 0; kk < FIN; kk += 16) {
        int kbase = kk >> 1;
        uint32_t a[2][4];
        #pragma unroll
        for (int mi = 0; mi < 2; mi++) {
            int r0 = r_base + mi * 16 + group;
            a[mi][0] = As[r0 * ASW + kbase + tig];
            a[mi][1] = As[(r0 + 8) * ASW + kbase + tig];
            a[mi][2] = As[r0 * ASW + kbase + tig + 4];
            a[mi][3] = As[(r0 + 8) * ASW + kbase + tig + 4];
        }
        #pragma unroll
        for (int ni = 0; ni < 4; ni++) {
            int nc = n_base + ni * 8 + group;
            uint32_t b0 = Ws[nc * WSW + kbase + tig];
            uint32_t b1 = Ws[nc * WSW + kbase + tig + 4];
            mma_f16(C[0][ni], a[0][0], a[0][1], a[0][2], a[0][3], b0, b1);
            mma_f16(C[1][ni], a[1][0], a[1][1], a[1][2], a[1][3], b0, b1);
        }
    }

    if (OUTSEL != 2) {
        #pragma unroll
        for (int ni = 0; ni < 4; ni++) {
            int col = n_base + ni * 8 + 2 * tig;
            float2 bb = __ldg((const float2*)&b[col]);
            #pragma unroll
            for (int mi = 0; mi < 2; mi++) {
                int row0 = base_row + r_base + mi * 16 + group;
                float o00 = fmaxf(C[mi][ni][0] + bb.x, 0.0f);
                float o01 = fmaxf(C[mi][ni][1] + bb.y, 0.0f);
                float o10 = fmaxf(C[mi][ni][2] + bb.x, 0.0f);
                float o11 = fmaxf(C[mi][ni][3] + bb.y, 0.0f);
                if (row0 < NN)     hout[(size_t)row0 * 64 + (col >> 1)]       = pack_f16(o00, o01);
                if (row0 + 8 < NN) hout[(size_t)(row0 + 8) * 64 + (col >> 1)] = pack_f16(o10, o11);
            }
        }
    } else {
        float* rowsum = (float*)As;
        __syncthreads();
        if (tid < 128) rowsum[tid] = 0.0f;
        __syncthreads();
        #pragma unroll
        for (int mi = 0; mi < 2; mi++) {
            #pragma unroll
            for (int half = 0; half < 2; half++) {
                float partial = 0.0f;
                #pragma unroll
                for (int ni = 0; ni < 4; ni++) {
                    int col = n_base + ni * 8 + 2 * tig;
                    float2 bb = __ldg((const float2*)&b[col]);
                    float v0 = fmaxf(C[mi][ni][2 * half]     + bb.x, 0.0f);
                    float v1 = fmaxf(C[mi][ni][2 * half + 1] + bb.y, 0.0f);
                    float2 wl = __ldg((const float2*)&Wl[col]);
                    partial += v0 * wl.x + v1 * wl.y;
                }
                partial += __shfl_xor_sync(0xFFFFFFFFu, partial, 1);
                partial += __shfl_xor_sync(0xFFFFFFFFu, partial, 2);
                if (tig == 0) {
                    int rloc = r_base + mi * 16 + group + 8 * half;
                    atomicAdd(&rowsum[rloc], partial);
                }
            }
        }
        __syncthreads();
        if (tid < 128) {
            int row = base_row + tid;
            if (row < NN) {
                float s = rowsum[tid] + __ldg(bl);
                out[row] = (s > 0.0f) ? s : 0.01f * s;
            }
        }
    }
}

// ---------------- launch ----------------
extern "C" void kernel_launch(void* const* d_in, const int* in_sizes, int n_in,
                              void* d_out, int out_size) {
    int ix = 0, ie = 1, iW1 = 2, ib1 = 3, iW2 = 4, ib2 = 5, iW3 = 6, ib3 = 7,
        iW4 = 8, ib4 = 9, iW5 = 10, ib5 = 11, iWl = 12, ibl = 13;
    if (n_in >= 14 && in_sizes[0] != 2 * NN) {
        if (in_sizes[0] == 64 && in_sizes[1] == 4096) {
            iW1 = 0; iW2 = 1; iW3 = 2; iW4 = 3; iW5 = 4; iWl = 5;
            ib1 = 6; ib2 = 7; ib3 = 8; ib4 = 9; ib5 = 10; ibl = 11;
            ie = 12; ix = 13;
        }
    }

    const float* x  = (const float*)d_in[ix];
    const void*  ei = d_in[ie];
    const float* W1 = (const float*)d_in[iW1];
    const float* b1 = (const float*)d_in[ib1];
    const float* W2 = (const float*)d_in[iW2];
    const float* b2 = (const float*)d_in[ib2];
    const float* W3 = (const float*)d_in[iW3];
    const float* b3 = (const float*)d_in[ib3];
    const float* W4 = (const float*)d_in[iW4];
    const float* b4 = (const float*)d_in[ib4];
    const float* W5 = (const float*)d_in[iW5];
    const float* b5 = (const float*)d_in[ib5];
    const float* Wl = (const float*)d_in[iWl];
    const float* bl = (const float*)d_in[ibl];
    float* out = (float*)d_out;

    const int sh32  = (128 * 20 + 128 * 20) * 4;   // 20,480 B
    const int sh128 = (128 * 68 + 128 * 68) * 4;   // 69,632 B
    cudaFuncSetAttribute(k_gemm<32,  0, 0>, cudaFuncAttributeMaxDynamicSharedMemorySize, sh32);
    cudaFuncSetAttribute(k_gemm<128, 1, 1>, cudaFuncAttributeMaxDynamicSharedMemorySize, sh128);
    cudaFuncSetAttribute(k_gemm<128, 2, 0>, cudaFuncAttributeMaxDynamicSharedMemorySize, sh128);
    cudaFuncSetAttribute(k_gemm<128, 3, 2>, cudaFuncAttributeMaxDynamicSharedMemorySize, sh128);

    // CSR + norms + W conversion
    k_zero <<<ZB + 104, 256>>>(ei, W2, W3, W4, W5);
    k_count<<<(EE + 255) / 256, 256>>>(ei);
    k_scanA<<<NBLK, SB>>>();
    k_scanC<<<NBLK, SB>>>();                 // folded middle scan + g_dis
    k_fill <<<(EE + 255) / 256, 256>>>(ei); // bumps g_row -> END-pointer convention

    // layers
    k_layer1<<<(NN + 255) / 256, 256>>>(x, W1, b1);             // x  -> hB [N,32] fp16
    k_agg32 <<<NN / 32, 256>>>();                               // hB -> C
    k_gemm<32,  0, 0><<<G128, 512, sh32 >>>(b2, Wl, bl, out);   // C  -> hA
    k_agg128<true ><<<NN / 32, 256>>>();                        // hA -> C
    k_gemm<128, 1, 1><<<G128, 512, sh128>>>(b3, Wl, bl, out);   // C  -> hB
    k_agg128<false><<<NN / 32, 256>>>();                        // hB -> C
    k_gemm<128, 2, 0><<<G128, 512, sh128>>>(b4, Wl, bl, out);   // C  -> hA
    k_agg128<true ><<<NN / 32, 256>>>();                        // hA -> C
    k_gemm<128, 3, 2><<<G128, 512, sh128>>>(b5, Wl, bl, out);   // C  -> out (fused final)
}